// round 1
// baseline (speedup 1.0000x reference)
#include <cuda_runtime.h>

#define EMBED 1024
#define NHEAD 16
#define HDIM  64
#define BATCH 2
#define SEQ   2048
#define MROWS (BATCH*SEQ)   // 4096

// Scratch (device globals: no allocation allowed in kernel_launch)
__device__ float g_q[BATCH*NHEAD*SEQ*HDIM];   // [B,H,S,D]
__device__ float g_k[BATCH*NHEAD*SEQ*HDIM];
__device__ float g_v[BATCH*NHEAD*SEQ*HDIM];
__device__ float g_ctx[MROWS*EMBED];          // [B*S, E]

// ---------------------------------------------------------------------------
// SGEMM: C[M,N] = A[M,K] @ B[K,N] + bias[N], M=4096, N=K=1024
// 128x128 block tile, BK=16, 256 threads, 8x8 per-thread micro-tile.
// mode==1: scatter output into [B,H,S,D] head layout (QKV projections)
// mode==0: plain row-major (output projection / context)
// ---------------------------------------------------------------------------
#define BM 128
#define BN 128
#define BK 16
#define TM 8
#define TN 8

__device__ __forceinline__ void sgemm_body(
    const float* __restrict__ A, const float* __restrict__ B,
    const float* __restrict__ bias, float* __restrict__ C, int head_layout)
{
    const int K = EMBED, N = EMBED;
    __shared__ float As[BK][BM + 4];   // transposed A tile, padded
    __shared__ float Bs[BK][BN];

    const int tid = threadIdx.x;
    const int tx = tid & 15;          // N direction
    const int ty = tid >> 4;          // M direction
    const int m0 = blockIdx.y * BM;
    const int n0 = blockIdx.x * BN;

    float acc[TM][TN];
#pragma unroll
    for (int i = 0; i < TM; i++)
#pragma unroll
        for (int j = 0; j < TN; j++) acc[i][j] = 0.f;

    for (int k0 = 0; k0 < K; k0 += BK) {
        // Load A tile (128x16), transposed into As[k][m]
#pragma unroll
        for (int i = 0; i < (BM * BK) / 256; i++) {   // 8
            int idx = tid + i * 256;
            int m = idx >> 4, k = idx & 15;
            As[k][m] = A[(size_t)(m0 + m) * K + k0 + k];
        }
        // Load B tile (16x128) with float4
#pragma unroll
        for (int i = 0; i < (BK * BN) / (256 * 4); i++) {  // 2
            int idx4 = tid + i * 256;
            int k = idx4 >> 5, n4 = idx4 & 31;
            float4 vv = *reinterpret_cast<const float4*>(
                &B[(size_t)(k0 + k) * N + n0 + n4 * 4]);
            *reinterpret_cast<float4*>(&Bs[k][n4 * 4]) = vv;
        }
        __syncthreads();

#pragma unroll
        for (int k = 0; k < BK; k++) {
            float a[TM], b[TN];
#pragma unroll
            for (int i = 0; i < TM; i++) a[i] = As[k][ty + i * 16];
#pragma unroll
            for (int j = 0; j < TN; j++) b[j] = Bs[k][tx + j * 16];
#pragma unroll
            for (int i = 0; i < TM; i++)
#pragma unroll
                for (int j = 0; j < TN; j++) acc[i][j] += a[i] * b[j];
        }
        __syncthreads();
    }

    // Epilogue
#pragma unroll
    for (int i = 0; i < TM; i++) {
        int m = m0 + ty + i * 16;
#pragma unroll
        for (int j = 0; j < TN; j++) {
            int n = n0 + tx + j * 16;
            float v = acc[i][j] + bias[n];
            if (head_layout) {
                int b = m >> 11, s = m & (SEQ - 1);
                int h = n >> 6, d = n & (HDIM - 1);
                C[((size_t)(b * NHEAD + h) * SEQ + s) * HDIM + d] = v;
            } else {
                C[(size_t)m * N + n] = v;
            }
        }
    }
}

extern "C" __global__ void __launch_bounds__(256)
qkv_kernel(const float* __restrict__ x,
           const float* __restrict__ Wq, const float* __restrict__ bq,
           const float* __restrict__ Wk, const float* __restrict__ bk,
           const float* __restrict__ Wv, const float* __restrict__ bv)
{
    const float* W; const float* bias; float* C;
    if (blockIdx.z == 0)      { W = Wq; bias = bq; C = g_q; }
    else if (blockIdx.z == 1) { W = Wk; bias = bk; C = g_k; }
    else                      { W = Wv; bias = bv; C = g_v; }
    sgemm_body(x, W, bias, C, 1);
}

extern "C" __global__ void __launch_bounds__(256)
oproj_kernel(const float* __restrict__ Wo, const float* __restrict__ bo,
             float* __restrict__ out)
{
    sgemm_body(g_ctx, Wo, bo, out, 0);
}

// ---------------------------------------------------------------------------
// Fused masked flash-attention (fp32, online softmax).
// One block handles (b, h, q-tile of 128). 256 threads.
// Per thread: 8 q-rows (ty+16i) x 4 k/d-cols (tx+16j).
// Row reductions via shfl over the 16 lanes that share ty (same warp).
// ---------------------------------------------------------------------------
#define TQ 128
#define TK 64
#define SP 65   // smem row stride (64 + 1, conflict-free column access)
#define ATTN_SMEM_FLOATS (TQ*SP + TK*SP + TK*SP + TQ*SP + TK)

extern "C" __global__ void __launch_bounds__(256)
attn_kernel(const int* __restrict__ mask)
{
    extern __shared__ float sm[];
    float* Qs  = sm;                 // [TQ][SP]
    float* Ks  = Qs + TQ * SP;       // [TK][SP]
    float* Vs  = Ks + TK * SP;       // [TK][SP]
    float* Ps  = Vs + TK * SP;       // [TQ][SP]
    float* msk = Ps + TQ * SP;       // [TK]

    const int tid = threadIdx.x;
    const int tx = tid & 15;
    const int ty = tid >> 4;
    const int b  = blockIdx.z;
    const int h  = blockIdx.y;
    const int q0 = blockIdx.x * TQ;

    const float* qbase = g_q + (size_t)(b * NHEAD + h) * SEQ * HDIM;
    const float* kbase = g_k + (size_t)(b * NHEAD + h) * SEQ * HDIM;
    const float* vbase = g_v + (size_t)(b * NHEAD + h) * SEQ * HDIM;
    const int*   mbase = mask + b * SEQ;

    // Load Q tile once
#pragma unroll
    for (int i = 0; i < (TQ * HDIM) / 256; i++) {   // 32
        int idx = tid + i * 256;
        int r = idx >> 6, d = idx & 63;
        Qs[r * SP + d] = qbase[(size_t)(q0 + r) * HDIM + d];
    }

    float m_i[8], l_i[8], o[8][4];
#pragma unroll
    for (int i = 0; i < 8; i++) {
        m_i[i] = -1e30f; l_i[i] = 0.f;
#pragma unroll
        for (int j = 0; j < 4; j++) o[i][j] = 0.f;
    }
    __syncthreads();

    for (int k0 = 0; k0 < SEQ; k0 += TK) {
        // Load K/V tiles + mask slice
#pragma unroll
        for (int i = 0; i < (TK * HDIM) / 256; i++) {   // 16
            int idx = tid + i * 256;
            int r = idx >> 6, d = idx & 63;
            Ks[r * SP + d] = kbase[(size_t)(k0 + r) * HDIM + d];
            Vs[r * SP + d] = vbase[(size_t)(k0 + r) * HDIM + d];
        }
        if (tid < TK) msk[tid] = (float)mbase[k0 + tid];
        __syncthreads();

        // S = Q @ K^T (per-thread 8x4)
        float s[8][4];
#pragma unroll
        for (int i = 0; i < 8; i++)
#pragma unroll
            for (int j = 0; j < 4; j++) s[i][j] = 0.f;

        for (int d = 0; d < HDIM; d++) {
            float aq[8], bk[4];
#pragma unroll
            for (int i = 0; i < 8; i++) aq[i] = Qs[(ty + 16 * i) * SP + d];
#pragma unroll
            for (int j = 0; j < 4; j++) bk[j] = Ks[(tx + 16 * j) * SP + d];
#pragma unroll
            for (int i = 0; i < 8; i++)
#pragma unroll
                for (int j = 0; j < 4; j++) s[i][j] += aq[i] * bk[j];
        }

        // scale 1/sqrt(D)=0.125, mask -> -1e30
        float mv[4];
#pragma unroll
        for (int j = 0; j < 4; j++) mv[j] = msk[tx + 16 * j];
#pragma unroll
        for (int i = 0; i < 8; i++)
#pragma unroll
            for (int j = 0; j < 4; j++)
                s[i][j] = (mv[j] != 0.f) ? s[i][j] * 0.125f : -1e30f;

        // Online softmax per row; the 16 lanes sharing ty hold one row set.
#pragma unroll
        for (int i = 0; i < 8; i++) {
            float mt = fmaxf(fmaxf(s[i][0], s[i][1]), fmaxf(s[i][2], s[i][3]));
#pragma unroll
            for (int off = 1; off < 16; off <<= 1)
                mt = fmaxf(mt, __shfl_xor_sync(0xffffffffu, mt, off));
            float mnew = fmaxf(m_i[i], mt);
            float a = __expf(m_i[i] - mnew);   // exactly 0 when new real max appears
            float ls = 0.f;
#pragma unroll
            for (int j = 0; j < 4; j++) {
                float p = __expf(s[i][j] - mnew);  // masked: exp(-1e30-m)=0
                s[i][j] = p;
                ls += p;
            }
#pragma unroll
            for (int off = 1; off < 16; off <<= 1)
                ls += __shfl_xor_sync(0xffffffffu, ls, off);
            l_i[i] = l_i[i] * a + ls;
            m_i[i] = mnew;
#pragma unroll
            for (int j = 0; j < 4; j++) o[i][j] *= a;
            int r = ty + 16 * i;
#pragma unroll
            for (int j = 0; j < 4; j++) Ps[r * SP + tx + 16 * j] = s[i][j];
        }
        __syncthreads();

        // O += P @ V
        for (int kk = 0; kk < TK; kk++) {
            float pv[8], vv[4];
#pragma unroll
            for (int i = 0; i < 8; i++) pv[i] = Ps[(ty + 16 * i) * SP + kk];
#pragma unroll
            for (int j = 0; j < 4; j++) vv[j] = Vs[kk * SP + tx + 16 * j];
#pragma unroll
            for (int i = 0; i < 8; i++)
#pragma unroll
                for (int j = 0; j < 4; j++) o[i][j] += pv[i] * vv[j];
        }
        __syncthreads();
    }

    // Write context in [B*S, E] layout (E col = h*64 + d)
#pragma unroll
    for (int i = 0; i < 8; i++) {
        int q = q0 + ty + 16 * i;
        float inv = (l_i[i] > 0.f) ? (1.f / l_i[i]) : 0.f;
#pragma unroll
        for (int j = 0; j < 4; j++) {
            int d = tx + 16 * j;
            g_ctx[(size_t)(b * SEQ + q) * EMBED + h * HDIM + d] = o[i][j] * inv;
        }
    }
}

// ---------------------------------------------------------------------------
extern "C" void kernel_launch(void* const* d_in, const int* in_sizes, int n_in,
                              void* d_out, int out_size)
{
    const float* x    = (const float*)d_in[0];
    const int*   mask = (const int*)d_in[1];
    const float* Wq   = (const float*)d_in[2];
    const float* bq   = (const float*)d_in[3];
    const float* Wk   = (const float*)d_in[4];
    const float* bk   = (const float*)d_in[5];
    const float* Wv   = (const float*)d_in[6];
    const float* bv   = (const float*)d_in[7];
    const float* Wo   = (const float*)d_in[8];
    const float* bo   = (const float*)d_in[9];
    float* out = (float*)d_out;

    (void)in_sizes; (void)n_in; (void)out_size;

    size_t attn_smem = (size_t)ATTN_SMEM_FLOATS * sizeof(float);
    cudaFuncSetAttribute(attn_kernel,
                         cudaFuncAttributeMaxDynamicSharedMemorySize,
                         (int)attn_smem);

    dim3 gq(EMBED / BN, MROWS / BM, 3);       // 8 x 32 x 3
    qkv_kernel<<<gq, 256>>>(x, Wq, bq, Wk, bk, Wv, bv);

    dim3 ga(SEQ / TQ, NHEAD, BATCH);          // 16 x 16 x 2
    attn_kernel<<<ga, 256, attn_smem>>>(mask);

    dim3 go(EMBED / BN, MROWS / BM, 1);       // 8 x 32
    oproj_kernel<<<go, 256>>>(Wo, bo, out);
}

// round 3
// speedup vs baseline: 3.0871x; 3.0871x over previous
#include <cuda_runtime.h>
#include <cuda_bf16.h>
#include <cstdint>

#define EMBED 1024
#define NHEAD 16
#define HDIM  64
#define BATCH 2
#define SEQ   2048
#define MROWS (BATCH*SEQ)   // 4096

// ---------------------------------------------------------------------------
// Device-global scratch. All bf16 data is stored PACKED: u32 = lo16:hi_part
// Actually: u32 = (hi_bf16 in bits[15:0]) | (lo_bf16 in bits[31:16]),
// where value ~= hi + lo (hi = bf16(v), lo = bf16(v - hi)).
// ---------------------------------------------------------------------------
__device__ uint32_t g_x2 [MROWS*EMBED];               // x packed [m][k]
__device__ uint32_t g_w2 [4*EMBED*EMBED];             // W^T packed [4][n][k]
__device__ uint32_t g_q2 [BATCH*NHEAD*SEQ*HDIM];      // Q packed [b,h,s,d] (pre-scaled by 0.125)
__device__ uint32_t g_k2 [BATCH*NHEAD*SEQ*HDIM];      // K packed [b,h,s,d]
__device__ uint32_t g_vt2[BATCH*NHEAD*HDIM*SEQ];      // V packed TRANSPOSED [b,h,d,s]
__device__ uint32_t g_c2 [MROWS*EMBED];               // ctx packed [m][e]

// ---------------------------------------------------------------------------
// Helpers
// ---------------------------------------------------------------------------
__device__ __forceinline__ uint32_t prmt(uint32_t a, uint32_t b, uint32_t sel) {
    uint32_t d;
    asm("prmt.b32 %0,%1,%2,%3;" : "=r"(d) : "r"(a), "r"(b), "r"(sel));
    return d;
}
// pack value into (hi,lo) split pair: hi in low 16 bits, lo in high 16 bits
__device__ __forceinline__ uint32_t pack_hilo(float v) {
    __nv_bfloat16 h = __float2bfloat16(v);
    __nv_bfloat16 l = __float2bfloat16(v - __bfloat162float(h));
    __nv_bfloat162 t(h, l);
    return *reinterpret_cast<uint32_t*>(&t);
}
// pack two floats as bf16x2: e0 -> low 16, e1 -> high 16
__device__ __forceinline__ uint32_t pk2(float e0, float e1) {
    uint32_t d;
    asm("cvt.rn.bf16x2.f32 %0, %1, %2;" : "=r"(d) : "f"(e1), "f"(e0));
    return d;
}

#define MMA16816(c, a, b0, b1)                                              \
    asm volatile("mma.sync.aligned.m16n8k16.row.col.f32.bf16.bf16.f32 "     \
        "{%0,%1,%2,%3}, {%4,%5,%6,%7}, {%8,%9}, {%0,%1,%2,%3};"             \
        : "+f"((c)[0]), "+f"((c)[1]), "+f"((c)[2]), "+f"((c)[3])            \
        : "r"((a)[0]), "r"((a)[1]), "r"((a)[2]), "r"((a)[3]),               \
          "r"(b0), "r"(b1))

// ---------------------------------------------------------------------------
// Conversion kernels
// ---------------------------------------------------------------------------
extern "C" __global__ void __launch_bounds__(256)
cvt_x_kernel(const float* __restrict__ src, int which)  // which: 0 -> g_x2
{
    uint32_t* dst = g_x2;
    (void)which;
    int i = (blockIdx.x * 256 + threadIdx.x) * 4;
    float4 v = *reinterpret_cast<const float4*>(src + i);
    uint4 o;
    o.x = pack_hilo(v.x); o.y = pack_hilo(v.y);
    o.z = pack_hilo(v.z); o.w = pack_hilo(v.w);
    *reinterpret_cast<uint4*>(dst + i) = o;
}

// Transpose + split the 4 weight matrices: g_w2[z][n][k] = split(W[k][n])
extern "C" __global__ void __launch_bounds__(256)
cvt_w_kernel(const float* __restrict__ Wq, const float* __restrict__ Wk,
             const float* __restrict__ Wv, const float* __restrict__ Wo)
{
    __shared__ float t[32][33];
    const float* W = (blockIdx.z == 0) ? Wq : (blockIdx.z == 1) ? Wk :
                     (blockIdx.z == 2) ? Wv : Wo;
    uint32_t* o2 = g_w2 + (size_t)blockIdx.z * EMBED * EMBED;
    int bx = blockIdx.x * 32;  // n base
    int by = blockIdx.y * 32;  // k base
    int tx = threadIdx.x, ty = threadIdx.y;
#pragma unroll
    for (int i = 0; i < 4; i++) {
        int r = ty + i * 8;
        t[r][tx] = W[(size_t)(by + r) * EMBED + bx + tx];
    }
    __syncthreads();
#pragma unroll
    for (int i = 0; i < 4; i++) {
        int r = ty + i * 8;              // local n
        float v = t[tx][r];              // = W[by+tx][bx+r]
        o2[(size_t)(bx + r) * EMBED + by + tx] = pack_hilo(v);
    }
}

// ---------------------------------------------------------------------------
// mma.sync split-bf16 GEMM: C[4096,1024] = A @ B^T(+bias)
// Block tile 128x128, BK=64, 256 threads (8 warps as 4m x 2n),
// warp tile 32x64 (2 m16-tiles x 8 n8-tiles).
// A2: packed [m][k], B2: packed [n][k].
// mode 0: fp32 out [m][n];  1: g_q2 (scale 0.125);  2: g_k2;  3: g_vt2.
// ---------------------------------------------------------------------------
#define GSMEM_BYTES (4*128*36*4)   // 73728

__device__ __forceinline__ void gemm_mma_body(
    const uint32_t* __restrict__ A2, const uint32_t* __restrict__ B2,
    const float* __restrict__ bias, int mode, float* __restrict__ outf,
    uint32_t* __restrict__ outp, float scale)
{
    extern __shared__ uint32_t sw[];
    uint32_t* Ash = sw;                 // [128][36] u32 words (72 bf16, pad 8)
    uint32_t* Asl = sw + 128*36;
    uint32_t* Bsh = sw + 2*128*36;
    uint32_t* Bsl = sw + 3*128*36;

    const int tid = threadIdx.x;
    const int lane = tid & 31, wid = tid >> 5;
    const int g = lane >> 2, t = lane & 3;
    const int wm = wid & 3, wn = wid >> 2;
    const int m0 = blockIdx.y * 128, n0 = blockIdx.x * 128;

    float acc[2][8][4];
#pragma unroll
    for (int a = 0; a < 2; a++)
#pragma unroll
        for (int b = 0; b < 8; b++)
#pragma unroll
            for (int c = 0; c < 4; c++) acc[a][b][c] = 0.f;

    for (int k0 = 0; k0 < EMBED; k0 += 64) {
        // stage A/B tiles: split packed u32 -> hi/lo bf16-pair words
#pragma unroll
        for (int i = 0; i < 8; i++) {
            int e4 = i * 256 + tid;
            int r = e4 >> 4, c = (e4 & 15) * 4;
            int w = r * 36 + (c >> 1);
            uint4 va = *reinterpret_cast<const uint4*>(&A2[(size_t)(m0 + r) * EMBED + k0 + c]);
            uint2 ah = make_uint2(prmt(va.x, va.y, 0x5410), prmt(va.z, va.w, 0x5410));
            uint2 al = make_uint2(prmt(va.x, va.y, 0x7632), prmt(va.z, va.w, 0x7632));
            *reinterpret_cast<uint2*>(&Ash[w]) = ah;
            *reinterpret_cast<uint2*>(&Asl[w]) = al;
            uint4 vb = *reinterpret_cast<const uint4*>(&B2[(size_t)(n0 + r) * EMBED + k0 + c]);
            uint2 bh = make_uint2(prmt(vb.x, vb.y, 0x5410), prmt(vb.z, vb.w, 0x5410));
            uint2 bl = make_uint2(prmt(vb.x, vb.y, 0x7632), prmt(vb.z, vb.w, 0x7632));
            *reinterpret_cast<uint2*>(&Bsh[w]) = bh;
            *reinterpret_cast<uint2*>(&Bsl[w]) = bl;
        }
        __syncthreads();

#pragma unroll
        for (int ks = 0; ks < 4; ks++) {
            uint32_t ah[2][4], al[2][4];
#pragma unroll
            for (int mt = 0; mt < 2; mt++) {
                int r = wm * 32 + mt * 16 + g;
                int base = r * 36 + ks * 8 + t;
                ah[mt][0] = Ash[base];          ah[mt][1] = Ash[base + 8*36];
                ah[mt][2] = Ash[base + 4];      ah[mt][3] = Ash[base + 8*36 + 4];
                al[mt][0] = Asl[base];          al[mt][1] = Asl[base + 8*36];
                al[mt][2] = Asl[base + 4];      al[mt][3] = Asl[base + 8*36 + 4];
            }
#pragma unroll
            for (int nt = 0; nt < 8; nt++) {
                int n = wn * 64 + nt * 8 + g;
                int base = n * 36 + ks * 8 + t;
                uint32_t bh0 = Bsh[base], bh1 = Bsh[base + 4];
                uint32_t bl0 = Bsl[base], bl1 = Bsl[base + 4];
#pragma unroll
                for (int mt = 0; mt < 2; mt++) {
                    MMA16816(acc[mt][nt], ah[mt], bh0, bh1);
                    MMA16816(acc[mt][nt], ah[mt], bl0, bl1);
                    MMA16816(acc[mt][nt], al[mt], bh0, bh1);
                }
            }
        }
        __syncthreads();
    }

    // epilogue
#pragma unroll
    for (int mt = 0; mt < 2; mt++) {
#pragma unroll
        for (int nt = 0; nt < 8; nt++) {
            int r0 = m0 + wm * 32 + mt * 16 + g;
            int r1 = r0 + 8;
            int c0 = n0 + wn * 64 + nt * 8 + 2 * t;
            float2 bb = *reinterpret_cast<const float2*>(&bias[c0]);
            float v0 = (acc[mt][nt][0] + bb.x) * scale;
            float v1 = (acc[mt][nt][1] + bb.y) * scale;
            float v2 = (acc[mt][nt][2] + bb.x) * scale;
            float v3 = (acc[mt][nt][3] + bb.y) * scale;
            if (mode == 0) {
                *reinterpret_cast<float2*>(&outf[(size_t)r0 * EMBED + c0]) = make_float2(v0, v1);
                *reinterpret_cast<float2*>(&outf[(size_t)r1 * EMBED + c0]) = make_float2(v2, v3);
            } else if (mode <= 2) {
                int hh = c0 >> 6, d = c0 & 63;
                int b0i = r0 >> 11, s0i = r0 & (SEQ - 1);
                int b1i = r1 >> 11, s1i = r1 & (SEQ - 1);
                uint2 p0 = make_uint2(pack_hilo(v0), pack_hilo(v1));
                uint2 p1 = make_uint2(pack_hilo(v2), pack_hilo(v3));
                *reinterpret_cast<uint2*>(&outp[((size_t)(b0i*NHEAD+hh)*SEQ + s0i)*HDIM + d]) = p0;
                *reinterpret_cast<uint2*>(&outp[((size_t)(b1i*NHEAD+hh)*SEQ + s1i)*HDIM + d]) = p1;
            } else {
                // V transposed: [b,h,d,s]
                int hh = c0 >> 6, d = c0 & 63;
                int b0i = r0 >> 11, s0i = r0 & (SEQ - 1);
                int b1i = r1 >> 11, s1i = r1 & (SEQ - 1);
                size_t base0 = (size_t)(b0i*NHEAD+hh)*HDIM*SEQ;
                size_t base1 = (size_t)(b1i*NHEAD+hh)*HDIM*SEQ;
                outp[base0 + (size_t)d * SEQ + s0i]       = pack_hilo(v0);
                outp[base0 + (size_t)(d+1) * SEQ + s0i]   = pack_hilo(v1);
                outp[base1 + (size_t)d * SEQ + s1i]       = pack_hilo(v2);
                outp[base1 + (size_t)(d+1) * SEQ + s1i]   = pack_hilo(v3);
            }
        }
    }
}

extern "C" __global__ void __launch_bounds__(256, 1)
qkv_mma_kernel(const float* __restrict__ bq, const float* __restrict__ bk,
               const float* __restrict__ bv)
{
    const int z = blockIdx.z;
    const uint32_t* B2 = g_w2 + (size_t)z * EMBED * EMBED;
    const float* bias = (z == 0) ? bq : (z == 1) ? bk : bv;
    uint32_t* outp = (z == 0) ? g_q2 : (z == 1) ? g_k2 : g_vt2;
    int mode = (z == 0) ? 1 : (z == 1) ? 2 : 3;
    float scale = (z == 0) ? 0.125f : 1.0f;   // fold 1/sqrt(64) into Q
    gemm_mma_body(g_x2, B2, bias, mode, nullptr, outp, scale);
}

extern "C" __global__ void __launch_bounds__(256, 1)
oproj_mma_kernel(const float* __restrict__ bo, float* __restrict__ out)
{
    gemm_mma_body(g_c2, g_w2 + (size_t)3 * EMBED * EMBED, bo, 0, out, nullptr, 1.0f);
}

// ---------------------------------------------------------------------------
// Flash attention on mma.sync, split-bf16 everywhere.
// Block: 128 q-rows, 8 warps (one m16 tile each), TK=128 per iteration.
// Q fragments live in registers (pre-scaled by 0.125 at projection).
// P stays in registers via the C-fragment -> A-fragment layout identity.
// ---------------------------------------------------------------------------
// smem (u32 words): Ksh[128][36] | Ksl[128][36] | Vth[64][68] | Vtl[64][68] | msk[128]
#define AT_KSH 0
#define AT_KSL (128*36)
#define AT_VTH (2*128*36)
#define AT_VTL (2*128*36 + 64*68)
#define AT_MSK (2*128*36 + 2*64*68)
#define ASMEM_WORDS (AT_MSK + 128)
#define ASMEM_BYTES (ASMEM_WORDS*4)     // 72704... computed below

extern "C" __global__ void __launch_bounds__(256, 1)
attn_mma_kernel(const int* __restrict__ mask)
{
    extern __shared__ uint32_t sw[];
    uint32_t* Ksh = sw + AT_KSH;
    uint32_t* Ksl = sw + AT_KSL;
    uint32_t* Vth = sw + AT_VTH;
    uint32_t* Vtl = sw + AT_VTL;
    float*    msk = reinterpret_cast<float*>(sw + AT_MSK);

    const int tid = threadIdx.x, lane = tid & 31, wid = tid >> 5;
    const int g = lane >> 2, t = lane & 3;
    const int b = blockIdx.z, h = blockIdx.y;
    const int q0 = blockIdx.x * 128;
    const int qw = wid * 16;                       // warp's local q base
    const size_t bh = (size_t)(b * NHEAD + h);
    const uint32_t* qb = g_q2 + bh * SEQ * HDIM;
    const uint32_t* kb = g_k2 + bh * SEQ * HDIM;
    const uint32_t* vb = g_vt2 + bh * HDIM * SEQ;
    const int* mb = mask + b * SEQ;

    // ---- stage Q packed into smem (stride 68 words, 16B aligned), build frags
#pragma unroll
    for (int i = 0; i < 8; i++) {
        int e4 = i * 256 + tid;
        int r = e4 >> 4, c = (e4 & 15) * 4;
        uint4 v = *reinterpret_cast<const uint4*>(&qb[(size_t)(q0 + r) * HDIM + c]);
        *reinterpret_cast<uint4*>(&sw[r * 68 + c]) = v;
    }
    __syncthreads();

    uint32_t qh[4][4], ql[4][4];
#pragma unroll
    for (int ks = 0; ks < 4; ks++) {
#pragma unroll
        for (int p = 0; p < 4; p++) {
            int row = qw + g + ((p & 1) ? 8 : 0);
            int col = ks * 16 + 2 * t + ((p >= 2) ? 8 : 0);
            uint2 e = *reinterpret_cast<uint2*>(&sw[row * 68 + col]);
            qh[ks][p] = prmt(e.x, e.y, 0x5410);
            ql[ks][p] = prmt(e.x, e.y, 0x7632);
        }
    }
    __syncthreads();

    float mrow[2] = {-1e30f, -1e30f};
    float lrow[2] = {0.f, 0.f};
    float o[8][4];
#pragma unroll
    for (int i = 0; i < 8; i++)
#pragma unroll
        for (int j = 0; j < 4; j++) o[i][j] = 0.f;

    for (int s0 = 0; s0 < SEQ; s0 += 128) {
        if (tid < 128) msk[tid] = (float)mb[s0 + tid];
        // stage K [128 s][64 d]
#pragma unroll
        for (int i = 0; i < 8; i++) {
            int e4 = i * 256 + tid;
            int r = e4 >> 4, c = (e4 & 15) * 4;
            int w = r * 36 + (c >> 1);
            uint4 v = *reinterpret_cast<const uint4*>(&kb[(size_t)(s0 + r) * HDIM + c]);
            *reinterpret_cast<uint2*>(&Ksh[w]) =
                make_uint2(prmt(v.x, v.y, 0x5410), prmt(v.z, v.w, 0x5410));
            *reinterpret_cast<uint2*>(&Ksl[w]) =
                make_uint2(prmt(v.x, v.y, 0x7632), prmt(v.z, v.w, 0x7632));
        }
        // stage Vt [64 d][128 s]
#pragma unroll
        for (int i = 0; i < 8; i++) {
            int e4 = i * 256 + tid;
            int d = e4 >> 5, s = (e4 & 31) * 4;
            int w = d * 68 + (s >> 1);
            uint4 v = *reinterpret_cast<const uint4*>(&vb[(size_t)d * SEQ + s0 + s]);
            *reinterpret_cast<uint2*>(&Vth[w]) =
                make_uint2(prmt(v.x, v.y, 0x5410), prmt(v.z, v.w, 0x5410));
            *reinterpret_cast<uint2*>(&Vtl[w]) =
                make_uint2(prmt(v.x, v.y, 0x7632), prmt(v.z, v.w, 0x7632));
        }
        __syncthreads();

        // ---- S = Q K^T (scale pre-folded into Q)
        float sc[16][4];
#pragma unroll
        for (int nt = 0; nt < 16; nt++)
#pragma unroll
            for (int j = 0; j < 4; j++) sc[nt][j] = 0.f;
#pragma unroll
        for (int ks = 0; ks < 4; ks++) {
#pragma unroll
            for (int nt = 0; nt < 16; nt++) {
                int base = (nt * 8 + g) * 36 + ks * 8 + t;
                uint32_t b0 = Ksh[base], b1 = Ksh[base + 4];
                uint32_t c0 = Ksl[base], c1 = Ksl[base + 4];
                MMA16816(sc[nt], qh[ks], b0, b1);
                MMA16816(sc[nt], qh[ks], c0, c1);
                MMA16816(sc[nt], ql[ks], b0, b1);
            }
        }

        // ---- mask
#pragma unroll
        for (int nt = 0; nt < 16; nt++) {
            float2 mv = *reinterpret_cast<float2*>(&msk[nt * 8 + 2 * t]);
            if (mv.x == 0.f) { sc[nt][0] = -1e30f; sc[nt][2] = -1e30f; }
            if (mv.y == 0.f) { sc[nt][1] = -1e30f; sc[nt][3] = -1e30f; }
        }

        // ---- online softmax (rows g and g+8; quad lanes share a row)
        float alpha[2];
#pragma unroll
        for (int rh = 0; rh < 2; rh++) {
            float mt_ = -1e30f;
#pragma unroll
            for (int nt = 0; nt < 16; nt++)
                mt_ = fmaxf(mt_, fmaxf(sc[nt][rh * 2 + 0], sc[nt][rh * 2 + 1]));
            mt_ = fmaxf(mt_, __shfl_xor_sync(0xffffffffu, mt_, 1));
            mt_ = fmaxf(mt_, __shfl_xor_sync(0xffffffffu, mt_, 2));
            float mn = fmaxf(mrow[rh], mt_);
            alpha[rh] = __expf(mrow[rh] - mn);
            float ls = 0.f;
#pragma unroll
            for (int nt = 0; nt < 16; nt++) {
                float p0 = __expf(sc[nt][rh * 2 + 0] - mn);
                float p1 = __expf(sc[nt][rh * 2 + 1] - mn);
                sc[nt][rh * 2 + 0] = p0;
                sc[nt][rh * 2 + 1] = p1;
                ls += p0 + p1;
            }
            ls += __shfl_xor_sync(0xffffffffu, ls, 1);
            ls += __shfl_xor_sync(0xffffffffu, ls, 2);
            lrow[rh] = lrow[rh] * alpha[rh] + ls;
            mrow[rh] = mn;
        }
#pragma unroll
        for (int dt = 0; dt < 8; dt++) {
            o[dt][0] *= alpha[0]; o[dt][1] *= alpha[0];
            o[dt][2] *= alpha[1]; o[dt][3] *= alpha[1];
        }

        // ---- O += P V   (P via C->A fragment identity, split hi/lo)
#pragma unroll
        for (int j = 0; j < 8; j++) {
            uint32_t ph[4], pl[4];
#pragma unroll
            for (int p = 0; p < 4; p++) {
                int nt = 2 * j + (p >> 1);
                int ix = (p & 1) * 2;
                float e0 = sc[nt][ix], e1 = sc[nt][ix + 1];
                __nv_bfloat16 h0 = __float2bfloat16(e0);
                __nv_bfloat16 h1 = __float2bfloat16(e1);
                __nv_bfloat162 hh(h0, h1);
                ph[p] = *reinterpret_cast<uint32_t*>(&hh);
                pl[p] = pk2(e0 - __bfloat162float(h0), e1 - __bfloat162float(h1));
            }
#pragma unroll
            for (int dt = 0; dt < 8; dt++) {
                int base = (dt * 8 + g) * 68 + j * 8 + t;
                uint32_t v0 = Vth[base], v1 = Vth[base + 4];
                uint32_t w0 = Vtl[base], w1 = Vtl[base + 4];
                MMA16816(o[dt], ph, v0, v1);
                MMA16816(o[dt], pl, v0, v1);
                MMA16816(o[dt], ph, w0, w1);
            }
        }
        __syncthreads();
    }

    // ---- write ctx packed [m][e]
    float inv0 = (lrow[0] > 0.f) ? (1.f / lrow[0]) : 0.f;
    float inv1 = (lrow[1] > 0.f) ? (1.f / lrow[1]) : 0.f;
    int r0 = q0 + qw + g, r1 = r0 + 8;
#pragma unroll
    for (int dt = 0; dt < 8; dt++) {
        int e = h * HDIM + dt * 8 + 2 * t;
        uint2 p0 = make_uint2(pack_hilo(o[dt][0] * inv0), pack_hilo(o[dt][1] * inv0));
        uint2 p1 = make_uint2(pack_hilo(o[dt][2] * inv1), pack_hilo(o[dt][3] * inv1));
        *reinterpret_cast<uint2*>(&g_c2[(size_t)(b * SEQ + r0) * EMBED + e]) = p0;
        *reinterpret_cast<uint2*>(&g_c2[(size_t)(b * SEQ + r1) * EMBED + e]) = p1;
    }
}

// ---------------------------------------------------------------------------
extern "C" void kernel_launch(void* const* d_in, const int* in_sizes, int n_in,
                              void* d_out, int out_size)
{
    const float* x    = (const float*)d_in[0];
    const int*   mask = (const int*)d_in[1];
    const float* Wq   = (const float*)d_in[2];
    const float* bq   = (const float*)d_in[3];
    const float* Wk   = (const float*)d_in[4];
    const float* bk   = (const float*)d_in[5];
    const float* Wv   = (const float*)d_in[6];
    const float* bv   = (const float*)d_in[7];
    const float* Wo   = (const float*)d_in[8];
    const float* bo   = (const float*)d_in[9];
    float* out = (float*)d_out;
    (void)in_sizes; (void)n_in; (void)out_size;

    cudaFuncSetAttribute(qkv_mma_kernel,
                         cudaFuncAttributeMaxDynamicSharedMemorySize, GSMEM_BYTES);
    cudaFuncSetAttribute(oproj_mma_kernel,
                         cudaFuncAttributeMaxDynamicSharedMemorySize, GSMEM_BYTES);
    cudaFuncSetAttribute(attn_mma_kernel,
                         cudaFuncAttributeMaxDynamicSharedMemorySize, ASMEM_BYTES);

    // 1. pack inputs
    cvt_x_kernel<<<(MROWS * EMBED) / 1024, 256>>>(x, 0);
    cvt_w_kernel<<<dim3(32, 32, 4), dim3(32, 8)>>>(Wq, Wk, Wv, Wo);

    // 2. QKV projections (tensor pipe)
    dim3 gq(EMBED / 128, MROWS / 128, 3);
    qkv_mma_kernel<<<gq, 256, GSMEM_BYTES>>>(bq, bk, bv);

    // 3. fused attention (tensor pipe)
    dim3 ga(SEQ / 128, NHEAD, BATCH);
    attn_mma_kernel<<<ga, 256, ASMEM_BYTES>>>(mask);

    // 4. output projection
    dim3 go(EMBED / 128, MROWS / 128, 1);
    oproj_mma_kernel<<<go, 256, GSMEM_BYTES>>>(bo, out);
}